// round 10
// baseline (speedup 1.0000x reference)
#include <cuda_runtime.h>
#include <cuda_bf16.h>
#include <cstdint>
#include <math.h>

#define NN 4096
#define DD 21
#define BSZ 4
#define QR 48            // 24 hi (21 classes + ones + 2 pad) + 24 lo
#define MT 128           // m rows per block
#define KCB 128          // bf16 k per staged chunk
#define HALFK 2048       // k per block (k-split 2)
#define NCHH (HALFK / KCB)   // 16 chunks
#define NITERS 5
#define THREADS 256

#define A_BYTES (MT * KCB * 2)            // 32768
#define B_BYTES (QR * KCB * 2)            // 12288
#define STAGE_BYTES (A_BYTES + B_BYTES)   // 45056
#define DSMEM_BYTES (2 * STAGE_BYTES)     // 90112

// Static device scratch (no allocation)
__device__ __nv_bfloat16 g_Wb[(size_t)BSZ * NN * NN];          // 128 MB bf16 W
__device__ __nv_bfloat16 g_QA[BSZ * QR * NN];                  // Q ping
__device__ __nv_bfloat16 g_QB[BSZ * QR * NN];                  // Q pong
__device__ float g_part[(size_t)BSZ * 32 * 2 * MT * QR];       // k-split partials
__device__ int   g_flag[BSZ * 32];                             // arrival counters

__device__ __forceinline__ uint32_t smem_u32(const void* p) {
    return (uint32_t)__cvta_generic_to_shared(p);
}
__device__ __forceinline__ void cp16(uint32_t dst, const void* src) {
    asm volatile("cp.async.cg.shared.global [%0], [%1], 16;\n" :: "r"(dst), "l"(src));
}
__device__ __forceinline__ uint32_t lds32(uint32_t a) {
    uint32_t v;
    asm volatile("ld.shared.b32 %0, [%1];" : "=r"(v) : "r"(a));
    return v;
}

// One-time W fp32 -> bf16 conversion (streams 256 MB in, 128 MB out)
__global__ void convertW(const float* __restrict__ W) {
    size_t i = ((size_t)blockIdx.x * 256 + threadIdx.x) * 8;
    float4 f0 = *(const float4*)(W + i);
    float4 f1 = *(const float4*)(W + i + 4);
    __nv_bfloat162 p0 = __float22bfloat162_rn(make_float2(f0.x, f0.y));
    __nv_bfloat162 p1 = __float22bfloat162_rn(make_float2(f0.z, f0.w));
    __nv_bfloat162 p2 = __float22bfloat162_rn(make_float2(f1.x, f1.y));
    __nv_bfloat162 p3 = __float22bfloat162_rn(make_float2(f1.z, f1.w));
    uint4 u;
    u.x = *(uint32_t*)&p0; u.y = *(uint32_t*)&p1;
    u.z = *(uint32_t*)&p2; u.w = *(uint32_t*)&p3;
    *(uint4*)(g_Wb + i) = u;
}

// Initial softmax over class dim; bf16 hi/lo split + ones/pad rows in BOTH buffers.
__global__ void softmax0_kernel(const float* __restrict__ seg) {
    int idx = blockIdx.x * blockDim.x + threadIdx.x;
    if (idx >= BSZ * NN) return;
    int b = idx >> 12;
    int n = idx & (NN - 1);
    const float* p = seg + (size_t)b * DD * NN + n;
    float v[DD];
    float mx = -3.4e38f;
#pragma unroll
    for (int d = 0; d < DD; d++) { v[d] = p[(size_t)d * NN]; mx = fmaxf(mx, v[d]); }
    float s = 0.f;
#pragma unroll
    for (int d = 0; d < DD; d++) { v[d] = __expf(v[d] - mx); s += v[d]; }
    float si = 1.0f / s;
    __nv_bfloat16* qa = g_QA + (size_t)b * QR * NN + n;
    __nv_bfloat16* qb = g_QB + (size_t)b * QR * NN + n;
#pragma unroll
    for (int d = 0; d < DD; d++) {
        float q = v[d] * si;
        __nv_bfloat16 h = __float2bfloat16(q);
        qa[(size_t)d * NN] = h;
        qa[(size_t)(24 + d) * NN] = __float2bfloat16(q - __bfloat162float(h));
    }
    __nv_bfloat16 one = __float2bfloat16(1.0f);
    __nv_bfloat16 zer = __float2bfloat16(0.0f);
    qa[21 * NN] = one; qa[22 * NN] = zer; qa[23 * NN] = zer;
    qa[45 * NN] = zer; qa[46 * NN] = zer; qa[47 * NN] = zer;
    qb[21 * NN] = one; qb[22 * NN] = zer; qb[23 * NN] = zer;
    qb[45 * NN] = zer; qb[46 * NN] = zer; qb[47 * NN] = zer;
}

// Half-K GEMM + fused k-split merge/epilogue (last-arriving block merges).
__global__ __launch_bounds__(THREADS, 2)
void crf_mma(const float* __restrict__ seg,
             const float* __restrict__ wts,
             float* __restrict__ out,
             int qsel, int last)
{
    extern __shared__ char dsm[];
    __shared__ float w_s[DD * DD];
    __shared__ int s_win;
    uint32_t dbase = smem_u32(dsm);

    int tid  = threadIdx.x;
    int wid  = tid >> 5;             // 0..7: warp owns m-rows [wid*16, wid*16+16)
    int lane = tid & 31;
    int tg   = lane >> 2;            // 0..7
    int tig  = lane & 3;             // 0..3
    int bid  = blockIdx.x;
    int b     = bid >> 6;            // 64 blocks per batch (32 mtiles x 2 halves)
    int mtile = (bid & 63) >> 1;
    int h     = bid & 1;
    int m0    = mtile * MT;

    const __nv_bfloat16* Qsel = qsel ? g_QB : g_QA;
    const __nv_bfloat16* Wbase = g_Wb + ((size_t)(b * NN + m0)) * NN + h * HALFK;
    const __nv_bfloat16* Qbase = Qsel + (size_t)b * QR * NN + h * HALFK;

    for (int i = tid; i < DD * DD; i += THREADS) w_s[i] = wts[i];

    // stage chunk c into stage buffer st
    auto stage = [&](int st, int c) {
        const __nv_bfloat16* ws = Wbase + c * KCB;
        uint32_t au = dbase + st * STAGE_BYTES;
#pragma unroll
        for (int i = tid; i < MT * (KCB / 8); i += THREADS) {   // 2048 granules
            int row = i >> 4;
            int g   = i & 15;
            cp16(au + row * 256 + ((g ^ (row & 7)) << 4),
                 ws + (size_t)row * NN + g * 8);
        }
        const __nv_bfloat16* qs = Qbase + c * KCB;
        uint32_t bu = dbase + st * STAGE_BYTES + A_BYTES;
#pragma unroll
        for (int i = tid; i < QR * (KCB / 8); i += THREADS) {   // 768 granules
            int row = i >> 4;
            int g   = i & 15;
            cp16(bu + row * 256 + ((g ^ (row & 7)) << 4),
                 qs + (size_t)row * NN + g * 8);
        }
        asm volatile("cp.async.commit_group;\n");
    };

    stage(0, 0);
    stage(1, 1);

    float acc[6][4];
#pragma unroll
    for (int nt = 0; nt < 6; nt++)
#pragma unroll
        for (int j = 0; j < 4; j++) acc[nt][j] = 0.f;

    for (int c = 0; c < NCHH; c++) {
        if (c < NCHH - 1) asm volatile("cp.async.wait_group 1;\n" ::: "memory");
        else              asm volatile("cp.async.wait_group 0;\n" ::: "memory");
        __syncthreads();

        uint32_t Ab = dbase + (c & 1) * STAGE_BYTES;
        uint32_t Bq = Ab + A_BYTES;
        uint32_t rowa = (uint32_t)(wid * 16 + tg);
        uint32_t ra = Ab + rowa * 256 + 4 * tig;
        uint32_t rb = ra + 8 * 256;

#pragma unroll
        for (int s = 0; s < KCB / 16; s++) {          // 8 k-steps of 16
            uint32_t sw0 = (uint32_t)(((2 * s)     ^ tg) << 4);
            uint32_t sw1 = (uint32_t)(((2 * s + 1) ^ tg) << 4);
            uint32_t a0 = lds32(ra + sw0);
            uint32_t a2 = lds32(ra + sw1);
            uint32_t a1 = lds32(rb + sw0);
            uint32_t a3 = lds32(rb + sw1);
#pragma unroll
            for (int nt = 0; nt < 6; nt++) {
                uint32_t db = Bq + (uint32_t)(nt * 8 + tg) * 256 + 4 * tig;
                uint32_t b0 = lds32(db + sw0);
                uint32_t b1 = lds32(db + sw1);
                asm volatile(
                    "mma.sync.aligned.m16n8k16.row.col.f32.bf16.bf16.f32 "
                    "{%0,%1,%2,%3}, {%4,%5,%6,%7}, {%8,%9}, {%0,%1,%2,%3};"
                    : "+f"(acc[nt][0]), "+f"(acc[nt][1]),
                      "+f"(acc[nt][2]), "+f"(acc[nt][3])
                    : "r"(a0), "r"(a1), "r"(a2), "r"(a3),
                      "r"(b0), "r"(b1));
            }
        }
        __syncthreads();
        if (c + 2 < NCHH) stage(c & 1, c + 2);
    }

    // write partials
    float* pb = g_part + (size_t)bid * MT * QR;
    int r = wid * 16 + tg;
#pragma unroll
    for (int nt = 0; nt < 6; nt++) {
        int col = nt * 8 + 2 * tig;
        *(float2*)(pb + (size_t)r * QR + col)       = make_float2(acc[nt][0], acc[nt][1]);
        *(float2*)(pb + (size_t)(r + 8) * QR + col) = make_float2(acc[nt][2], acc[nt][3]);
    }

    // ---- no-spin k-split handoff: second arriver merges + runs epilogue ----
    __threadfence();
    __syncthreads();
    if (tid == 0)
        s_win = atomicAdd(&g_flag[bid >> 1], 1) & 1;   // odd => both halves done
    __syncthreads();
    if (!s_win) return;
    __threadfence();   // acquire: partner's partial writes now visible via L2

    if (tid < MT) {
        int m = m0 + tid;
        const float* p0 = g_part + (size_t)((bid >> 1) << 1) * MT * QR + (size_t)tid * QR;
        const float* p1 = p0 + (size_t)MT * QR;

        float a2[DD + 1];
#pragma unroll
        for (int d = 0; d <= DD; d++)
            a2[d] = (__ldcg(p0 + d) + __ldcg(p1 + d)) +
                    (__ldcg(p0 + 24 + d) + __ldcg(p1 + 24 + d));

        float rinv = 1.0f / a2[DD];       // rowsum via ones-row (col 21)
        float sd[DD];
#pragma unroll
        for (int e = 0; e < DD; e++) sd[e] = a2[e] * rinv;

        float o[DD];
#pragma unroll
        for (int d = 0; d < DD; d++) {
            float u = 0.f;
#pragma unroll
            for (int e = 0; e < DD; e++) u = fmaf(w_s[d * DD + e], sd[e], u);
            o[d] = seg[((size_t)(b * DD + d)) * NN + m] - u;
        }

        if (last) {
#pragma unroll
            for (int d = 0; d < DD; d++)
                out[((size_t)(b * DD + d)) * NN + m] = o[d];
        } else {
            float mx = -3.4e38f;
#pragma unroll
            for (int d = 0; d < DD; d++) mx = fmaxf(mx, o[d]);
            float ssum = 0.f;
            float ex[DD];
#pragma unroll
            for (int d = 0; d < DD; d++) { ex[d] = __expf(o[d] - mx); ssum += ex[d]; }
            float si = 1.0f / ssum;
            __nv_bfloat16* qo = (qsel ? g_QA : g_QB) + (size_t)b * QR * NN + m;
#pragma unroll
            for (int d = 0; d < DD; d++) {
                float q = ex[d] * si;
                __nv_bfloat16 hb = __float2bfloat16(q);
                qo[(size_t)d * NN] = hb;
                qo[(size_t)(24 + d) * NN] = __float2bfloat16(q - __bfloat162float(hb));
            }
        }
    }
}

extern "C" void kernel_launch(void* const* d_in, const int* in_sizes, int n_in,
                              void* d_out, int out_size)
{
    const float* seg = nullptr;
    const float* W   = nullptr;
    const float* wts = nullptr;
    for (int i = 0; i < n_in; i++) {
        if (in_sizes[i] == BSZ * DD * NN)       seg = (const float*)d_in[i];
        else if (in_sizes[i] == BSZ * NN * NN)  W   = (const float*)d_in[i];
        else if (in_sizes[i] == DD * DD)        wts = (const float*)d_in[i];
    }

    cudaFuncSetAttribute(crf_mma, cudaFuncAttributeMaxDynamicSharedMemorySize,
                         DSMEM_BYTES);

    convertW<<<32768, 256>>>(W);                       // 64M elems / (256*8)
    softmax0_kernel<<<(BSZ * NN) / 256, 256>>>(seg);
    for (int it = 0; it < NITERS; it++) {
        crf_mma<<<BSZ * 64, THREADS, DSMEM_BYTES>>>(
            seg, wts, (float*)d_out, it & 1, (it == NITERS - 1) ? 1 : 0);
    }
}

// round 11
// speedup vs baseline: 1.4438x; 1.4438x over previous
#include <cuda_runtime.h>
#include <cuda_bf16.h>
#include <cstdint>
#include <math.h>

#define NN 4096
#define DD 21
#define BSZ 4
#define QR 48            // 24 hi (21 classes + ones + 2 pad) + 24 lo
#define MT 128           // m rows per block
#define KCB 128          // bf16 k per staged chunk
#define HALFK 2048       // k per block (k-split 2)
#define NCHH (HALFK / KCB)   // 16 chunks
#define NITERS 5
#define THREADS 256

#define A_BYTES (MT * KCB * 2)            // 32768
#define B_BYTES (QR * KCB * 2)            // 12288
#define STAGE_BYTES (A_BYTES + B_BYTES)   // 45056
#define DSMEM_BYTES (2 * STAGE_BYTES)     // 90112

// Static device scratch (no allocation)
__device__ __nv_bfloat16 g_Wb[(size_t)BSZ * NN * NN];          // 128 MB bf16 W
__device__ __nv_bfloat16 g_QA[BSZ * QR * NN];                  // Q ping
__device__ __nv_bfloat16 g_QB[BSZ * QR * NN];                  // Q pong
__device__ float g_part[(size_t)BSZ * 32 * 2 * MT * QR];       // k-split partials

__device__ __forceinline__ uint32_t smem_u32(const void* p) {
    return (uint32_t)__cvta_generic_to_shared(p);
}
__device__ __forceinline__ void cp16(uint32_t dst, const void* src) {
    asm volatile("cp.async.cg.shared.global [%0], [%1], 16;\n" :: "r"(dst), "l"(src));
}
__device__ __forceinline__ uint32_t lds32(uint32_t a) {
    uint32_t v;
    asm volatile("ld.shared.b32 %0, [%1];" : "=r"(v) : "r"(a));
    return v;
}

// One-time W fp32 -> bf16 conversion (streams 256 MB in, 128 MB out)
__global__ void convertW(const float* __restrict__ W) {
    size_t i = ((size_t)blockIdx.x * 256 + threadIdx.x) * 8;
    float4 f0 = *(const float4*)(W + i);
    float4 f1 = *(const float4*)(W + i + 4);
    __nv_bfloat162 p0 = __float22bfloat162_rn(make_float2(f0.x, f0.y));
    __nv_bfloat162 p1 = __float22bfloat162_rn(make_float2(f0.z, f0.w));
    __nv_bfloat162 p2 = __float22bfloat162_rn(make_float2(f1.x, f1.y));
    __nv_bfloat162 p3 = __float22bfloat162_rn(make_float2(f1.z, f1.w));
    uint4 u;
    u.x = *(uint32_t*)&p0; u.y = *(uint32_t*)&p1;
    u.z = *(uint32_t*)&p2; u.w = *(uint32_t*)&p3;
    *(uint4*)(g_Wb + i) = u;
}

// Initial softmax over class dim; bf16 hi/lo split + ones/pad rows in BOTH buffers.
__global__ void softmax0_kernel(const float* __restrict__ seg) {
    int idx = blockIdx.x * blockDim.x + threadIdx.x;
    if (idx >= BSZ * NN) return;
    int b = idx >> 12;
    int n = idx & (NN - 1);
    const float* p = seg + (size_t)b * DD * NN + n;
    float v[DD];
    float mx = -3.4e38f;
#pragma unroll
    for (int d = 0; d < DD; d++) { v[d] = p[(size_t)d * NN]; mx = fmaxf(mx, v[d]); }
    float s = 0.f;
#pragma unroll
    for (int d = 0; d < DD; d++) { v[d] = __expf(v[d] - mx); s += v[d]; }
    float si = 1.0f / s;
    __nv_bfloat16* qa = g_QA + (size_t)b * QR * NN + n;
    __nv_bfloat16* qb = g_QB + (size_t)b * QR * NN + n;
#pragma unroll
    for (int d = 0; d < DD; d++) {
        float q = v[d] * si;
        __nv_bfloat16 h = __float2bfloat16(q);
        qa[(size_t)d * NN] = h;
        qa[(size_t)(24 + d) * NN] = __float2bfloat16(q - __bfloat162float(h));
    }
    __nv_bfloat16 one = __float2bfloat16(1.0f);
    __nv_bfloat16 zer = __float2bfloat16(0.0f);
    qa[21 * NN] = one; qa[22 * NN] = zer; qa[23 * NN] = zer;
    qa[45 * NN] = zer; qa[46 * NN] = zer; qa[47 * NN] = zer;
    qb[21 * NN] = one; qb[22 * NN] = zer; qb[23 * NN] = zer;
    qb[45 * NN] = zer; qb[46 * NN] = zer; qb[47 * NN] = zer;
}

// Half-K GEMM: partials[b][mtile][h][128][48] = W_bf16[m, hK..hK+2048) @ Q^T
__global__ __launch_bounds__(THREADS, 2)
void crf_mma(int qsel)
{
    extern __shared__ char dsm[];
    uint32_t dbase = smem_u32(dsm);

    int tid  = threadIdx.x;
    int wid  = tid >> 5;             // 0..7: warp owns m-rows [wid*16, wid*16+16)
    int lane = tid & 31;
    int tg   = lane >> 2;            // 0..7
    int tig  = lane & 3;             // 0..3
    int bid  = blockIdx.x;
    int b     = bid >> 6;            // 64 blocks per batch (32 mtiles x 2 halves)
    int mtile = (bid & 63) >> 1;
    int h     = bid & 1;
    int m0    = mtile * MT;

    const __nv_bfloat16* Qsel = qsel ? g_QB : g_QA;
    const __nv_bfloat16* Wbase = g_Wb + ((size_t)(b * NN + m0)) * NN + h * HALFK;
    const __nv_bfloat16* Qbase = Qsel + (size_t)b * QR * NN + h * HALFK;

    // stage chunk c into stage buffer st
    auto stage = [&](int st, int c) {
        const __nv_bfloat16* ws = Wbase + c * KCB;
        uint32_t au = dbase + st * STAGE_BYTES;
#pragma unroll
        for (int i = tid; i < MT * (KCB / 8); i += THREADS) {   // 2048 granules
            int row = i >> 4;
            int g   = i & 15;
            cp16(au + row * 256 + ((g ^ (row & 7)) << 4),
                 ws + (size_t)row * NN + g * 8);
        }
        const __nv_bfloat16* qs = Qbase + c * KCB;
        uint32_t bu = dbase + st * STAGE_BYTES + A_BYTES;
#pragma unroll
        for (int i = tid; i < QR * (KCB / 8); i += THREADS) {   // 768 granules
            int row = i >> 4;
            int g   = i & 15;
            cp16(bu + row * 256 + ((g ^ (row & 7)) << 4),
                 qs + (size_t)row * NN + g * 8);
        }
        asm volatile("cp.async.commit_group;\n");
    };

    stage(0, 0);
    stage(1, 1);

    float acc[6][4];
#pragma unroll
    for (int nt = 0; nt < 6; nt++)
#pragma unroll
        for (int j = 0; j < 4; j++) acc[nt][j] = 0.f;

    for (int c = 0; c < NCHH; c++) {
        if (c < NCHH - 1) asm volatile("cp.async.wait_group 1;\n" ::: "memory");
        else              asm volatile("cp.async.wait_group 0;\n" ::: "memory");
        __syncthreads();

        uint32_t Ab = dbase + (c & 1) * STAGE_BYTES;
        uint32_t Bq = Ab + A_BYTES;
        uint32_t rowa = (uint32_t)(wid * 16 + tg);
        uint32_t ra = Ab + rowa * 256 + 4 * tig;
        uint32_t rb = ra + 8 * 256;

#pragma unroll
        for (int s = 0; s < KCB / 16; s++) {          // 8 k-steps of 16
            uint32_t sw0 = (uint32_t)(((2 * s)     ^ tg) << 4);
            uint32_t sw1 = (uint32_t)(((2 * s + 1) ^ tg) << 4);
            uint32_t a0 = lds32(ra + sw0);
            uint32_t a2 = lds32(ra + sw1);
            uint32_t a1 = lds32(rb + sw0);
            uint32_t a3 = lds32(rb + sw1);
#pragma unroll
            for (int nt = 0; nt < 6; nt++) {
                uint32_t db = Bq + (uint32_t)(nt * 8 + tg) * 256 + 4 * tig;
                uint32_t b0 = lds32(db + sw0);
                uint32_t b1 = lds32(db + sw1);
                asm volatile(
                    "mma.sync.aligned.m16n8k16.row.col.f32.bf16.bf16.f32 "
                    "{%0,%1,%2,%3}, {%4,%5,%6,%7}, {%8,%9}, {%0,%1,%2,%3};"
                    : "+f"(acc[nt][0]), "+f"(acc[nt][1]),
                      "+f"(acc[nt][2]), "+f"(acc[nt][3])
                    : "r"(a0), "r"(a1), "r"(a2), "r"(a3),
                      "r"(b0), "r"(b1));
            }
        }
        __syncthreads();
        if (c + 2 < NCHH) stage(c & 1, c + 2);
    }

    // write partials (deterministic; merged by crf_ep)
    float* pb = g_part + (size_t)bid * MT * QR;
    int r = wid * 16 + tg;
#pragma unroll
    for (int nt = 0; nt < 6; nt++) {
        int col = nt * 8 + 2 * tig;
        *(float2*)(pb + (size_t)r * QR + col)       = make_float2(acc[nt][0], acc[nt][1]);
        *(float2*)(pb + (size_t)(r + 8) * QR + col) = make_float2(acc[nt][2], acc[nt][3]);
    }
}

// Merge k-split partials + fused epilogue. Partials staged through smem with
// fully-coalesced float4 loads (the k-halves are summed during the load).
__global__ __launch_bounds__(256)
void crf_ep(const float* __restrict__ seg,
            const float* __restrict__ wts,
            float* __restrict__ out,
            int qsel, int last)
{
    __shared__ float w_s[DD * DD];
    __shared__ float sp[MT][QR + 1];     // pitch 49: conflict-free row reads
    int tid = threadIdx.x;
    int bid = blockIdx.x;            // BSZ*32 blocks
    int b = bid >> 5;
    int mtile = bid & 31;
    for (int i = tid; i < DD * DD; i += 256) w_s[i] = wts[i];

    const float* pb = g_part + (size_t)(bid * 2) * MT * QR;
    // coalesced: thread loads float4 from both halves, stores their sum
#pragma unroll
    for (int i = tid; i < MT * QR / 4; i += 256) {    // 1536 float4s
        float4 v0 = *(const float4*)(pb + (size_t)i * 4);
        float4 v1 = *(const float4*)(pb + (size_t)MT * QR + (size_t)i * 4);
        int r = (i * 4) / QR;
        int c = (i * 4) % QR;                          // QR%4==0: same row
        sp[r][c]     = v0.x + v1.x;
        sp[r][c + 1] = v0.y + v1.y;
        sp[r][c + 2] = v0.z + v1.z;
        sp[r][c + 3] = v0.w + v1.w;
    }
    __syncthreads();

    if (tid < MT) {
        int m = mtile * MT + tid;
        float a2[DD + 1];
#pragma unroll
        for (int d = 0; d <= DD; d++) a2[d] = sp[tid][d] + sp[tid][24 + d];

        float rinv = 1.0f / a2[DD];       // rowsum via ones-row (col 21)
        float sd[DD];
#pragma unroll
        for (int e = 0; e < DD; e++) sd[e] = a2[e] * rinv;

        float o[DD];
#pragma unroll
        for (int d = 0; d < DD; d++) {
            float u = 0.f;
#pragma unroll
            for (int e = 0; e < DD; e++) u = fmaf(w_s[d * DD + e], sd[e], u);
            o[d] = seg[((size_t)(b * DD + d)) * NN + m] - u;
        }

        if (last) {
#pragma unroll
            for (int d = 0; d < DD; d++)
                out[((size_t)(b * DD + d)) * NN + m] = o[d];
        } else {
            float mx = -3.4e38f;
#pragma unroll
            for (int d = 0; d < DD; d++) mx = fmaxf(mx, o[d]);
            float ssum = 0.f;
            float ex[DD];
#pragma unroll
            for (int d = 0; d < DD; d++) { ex[d] = __expf(o[d] - mx); ssum += ex[d]; }
            float si = 1.0f / ssum;
            __nv_bfloat16* qo = (qsel ? g_QA : g_QB) + (size_t)b * QR * NN + m;
#pragma unroll
            for (int d = 0; d < DD; d++) {
                float q = ex[d] * si;
                __nv_bfloat16 hb = __float2bfloat16(q);
                qo[(size_t)d * NN] = hb;
                qo[(size_t)(24 + d) * NN] = __float2bfloat16(q - __bfloat162float(hb));
            }
        }
    }
}

extern "C" void kernel_launch(void* const* d_in, const int* in_sizes, int n_in,
                              void* d_out, int out_size)
{
    const float* seg = nullptr;
    const float* W   = nullptr;
    const float* wts = nullptr;
    for (int i = 0; i < n_in; i++) {
        if (in_sizes[i] == BSZ * DD * NN)       seg = (const float*)d_in[i];
        else if (in_sizes[i] == BSZ * NN * NN)  W   = (const float*)d_in[i];
        else if (in_sizes[i] == DD * DD)        wts = (const float*)d_in[i];
    }

    cudaFuncSetAttribute(crf_mma, cudaFuncAttributeMaxDynamicSharedMemorySize,
                         DSMEM_BYTES);

    convertW<<<32768, 256>>>(W);                       // 64M elems / (256*8)
    softmax0_kernel<<<(BSZ * NN) / 256, 256>>>(seg);
    for (int it = 0; it < NITERS; it++) {
        crf_mma<<<BSZ * 64, THREADS, DSMEM_BYTES>>>(it & 1);
        crf_ep<<<BSZ * 32, 256>>>(seg, wts, (float*)d_out,
                                  it & 1, (it == NITERS - 1) ? 1 : 0);
    }
}